// round 14
// baseline (speedup 1.0000x reference)
#include <cuda_runtime.h>
#include <cuda_bf16.h>
#include <math.h>

// Shapes
#define BB 16
#define NN 256
#define DD 256
#define HH 8
#define HD 32
#define PD 4
#define RATIO 4
#define ROWS (BB*NN)            // 4096
#define PAIR_ROWS (BB*NN*NN)    // 1048576

// ---------------- scratch (device globals, no allocation) ----------------
__device__ float g_xn [ROWS*DD];        // 4 MB
__device__ float g_qkv[ROWS*3*DD];      // 12 MB
__device__ float g_biasT[BB*HH*NN*NN];  // 33.5 MB  [B,H,N,N]
__device__ float g_xa [ROWS*DD];        // 4 MB  [B,N,H*HD]
__device__ float g_x1 [ROWS*DD];        // 4 MB
__device__ float g_m1 [ROWS*RATIO*DD];  // 16 MB

// Branchless gelu via Abramowitz-Stegun 7.1.26 erf (|eps| <= 1.5e-7).
__device__ __forceinline__ float gelu_exact(float x) {
    float z  = x * 0.70710678118654752f;
    float az = fabsf(z);
    float t  = __fdividef(1.0f, fmaf(0.3275911f, az, 1.0f));
    float p  = t*(0.254829592f + t*(-0.284496736f + t*(1.421413741f
                  + t*(-1.453152027f + t*1.061405429f))));
    float e  = __expf(-az*az);
    float erfv = copysignf(fmaf(-p, e, 1.0f), z);
    return 0.5f*x*(1.0f + erfv);
}

__device__ __forceinline__ unsigned f2tf32(float x) {
    unsigned r;
    asm("cvt.rna.tf32.f32 %0, %1;" : "=r"(r) : "f"(x));
    return r;
}

__device__ __forceinline__ void mma_tf32(
    float& c0, float& c1, float& c2, float& c3,
    unsigned a0, unsigned a1, unsigned a2, unsigned a3,
    unsigned b0, unsigned b1)
{
    asm volatile(
        "mma.sync.aligned.m16n8k8.row.col.f32.tf32.tf32.f32 "
        "{%0,%1,%2,%3}, {%4,%5,%6,%7}, {%8,%9}, {%0,%1,%2,%3};"
        : "+f"(c0), "+f"(c1), "+f"(c2), "+f"(c3)
        : "r"(a0), "r"(a1), "r"(a2), "r"(a3), "r"(b0), "r"(b1));
}

__device__ __forceinline__ unsigned sptr(const void* p) {
    return (unsigned)__cvta_generic_to_shared(p);
}
__device__ __forceinline__ void cp16(unsigned s, const float* g) {
    asm volatile("cp.async.cg.shared.global [%0], [%1], 16;" :: "r"(s), "l"(g));
}

// ---------------- pairwise MLP (tf32 tensor cores) ----------------
#define H1S 68   // smem row stride for h1 (conflict-free fragment loads)
__global__ __launch_bounds__(256) void pairwise_kernel(
    const float* __restrict__ u,
    const float* __restrict__ w1, const float* __restrict__ b1,
    const float* __restrict__ w2, const float* __restrict__ b2,
    const float* __restrict__ w3, const float* __restrict__ b3,
    float* __restrict__ biasOut)
{
    extern __shared__ float dsm[];
    unsigned* h1s = (unsigned*)dsm;                 // 128*68
    unsigned* w2f = h1s + 128*H1S;                  // 4096 (fragment layout)
    float*    w3s = (float*)(w2f + 4096);           // 512
    float*    b2s = w3s + 512;                      // 64
    float*    b3s = b2s + 64;                       // 8
    float*    w1s = b3s + 8;                        // 256
    float*    b1s = w1s + 256;                      // 64

    int tid = threadIdx.x;
    int lane = tid & 31, warp = tid >> 5;
    int tig = lane & 3, gid = lane >> 2;

    if (tid < 64)  b1s[tid] = b1[tid];
    if (tid < 64)  b2s[tid] = b2[tid];
    if (tid < 8)   b3s[tid] = b3[tid];
    w1s[tid] = w1[tid];
    for (int i = tid; i < 512; i += 256) w3s[i] = w3[i];
    for (int idx = tid; idx < 4096; idx += 256) {
        int tile = idx >> 6;          // kt*8 + nt
        int pos  = idx & 63;
        int l    = pos >> 1, which = pos & 1;
        int kt = tile >> 3, nt = tile & 7;
        int ltig = l & 3, lgid = l >> 2;
        int k = kt*8 + ltig + which*4;
        int n = nt*8 + lgid;
        w2f[tile*64 + l*2 + which] = f2tf32(w2[k*64 + n]);
    }

    {
        int row = tid >> 1;                 // 0..127
        int c0  = (tid & 1) * 32;
        long gr = (long)blockIdx.x * 128 + row;
        float4 uv = ((const float4*)u)[gr];
        unsigned* dst = h1s + row*H1S + c0;
#pragma unroll
        for (int cc = 0; cc < 32; cc += 4) {
            unsigned pk[4];
#pragma unroll
            for (int q = 0; q < 4; q++) {
                int c = c0 + cc + q;
                float t = b1s[c] + uv.x*w1s[c] + uv.y*w1s[64+c]
                                 + uv.z*w1s[128+c] + uv.w*w1s[192+c];
                pk[q] = f2tf32(gelu_exact(t));
            }
            *(uint4*)&dst[cc] = make_uint4(pk[0], pk[1], pk[2], pk[3]);
        }
    }
    __syncthreads();

    float c[8][4];
#pragma unroll
    for (int nt = 0; nt < 8; nt++)
#pragma unroll
        for (int q = 0; q < 4; q++) c[nt][q] = 0.f;

    const unsigned* h1w = h1s + (warp*16 + gid)*H1S;
#pragma unroll
    for (int kt = 0; kt < 8; kt++) {
        unsigned a0 = h1w[kt*8 + tig];
        unsigned a1 = h1w[8*H1S + kt*8 + tig];
        unsigned a2 = h1w[kt*8 + tig + 4];
        unsigned a3 = h1w[8*H1S + kt*8 + tig + 4];
        const uint2* bf = (const uint2*)(w2f + kt*8*64);
#pragma unroll
        for (int nt = 0; nt < 8; nt++) {
            uint2 b = bf[nt*32 + lane];
            mma_tf32(c[nt][0], c[nt][1], c[nt][2], c[nt][3],
                     a0, a1, a2, a3, b.x, b.y);
        }
    }

    float acc0[8], acc1[8];
#pragma unroll
    for (int h = 0; h < 8; h++) { acc0[h] = 0.f; acc1[h] = 0.f; }

#pragma unroll
    for (int nt = 0; nt < 8; nt++) {
        int col0 = nt*8 + tig*2;
        float g00 = gelu_exact(c[nt][0] + b2s[col0]);
        float g01 = gelu_exact(c[nt][1] + b2s[col0+1]);
        float g10 = gelu_exact(c[nt][2] + b2s[col0]);
        float g11 = gelu_exact(c[nt][3] + b2s[col0+1]);
        const float4* w3r = (const float4*)&w3s[col0*8];
        float4 wa0 = w3r[0], wa1 = w3r[1];
        float4 wb0 = w3r[2], wb1 = w3r[3];
        acc0[0] += g00*wa0.x + g01*wb0.x;  acc1[0] += g10*wa0.x + g11*wb0.x;
        acc0[1] += g00*wa0.y + g01*wb0.y;  acc1[1] += g10*wa0.y + g11*wb0.y;
        acc0[2] += g00*wa0.z + g01*wb0.z;  acc1[2] += g10*wa0.z + g11*wb0.z;
        acc0[3] += g00*wa0.w + g01*wb0.w;  acc1[3] += g10*wa0.w + g11*wb0.w;
        acc0[4] += g00*wa1.x + g01*wb1.x;  acc1[4] += g10*wa1.x + g11*wb1.x;
        acc0[5] += g00*wa1.y + g01*wb1.y;  acc1[5] += g10*wa1.y + g11*wb1.y;
        acc0[6] += g00*wa1.z + g01*wb1.z;  acc1[6] += g10*wa1.z + g11*wb1.z;
        acc0[7] += g00*wa1.w + g01*wb1.w;  acc1[7] += g10*wa1.w + g11*wb1.w;
    }

#pragma unroll
    for (int h = 0; h < 8; h++) {
        acc0[h] += __shfl_xor_sync(0xffffffffu, acc0[h], 1);
        acc1[h] += __shfl_xor_sync(0xffffffffu, acc1[h], 1);
    }
#pragma unroll
    for (int h = 0; h < 8; h++) {
        acc0[h] += __shfl_xor_sync(0xffffffffu, acc0[h], 2);
        acc1[h] += __shfl_xor_sync(0xffffffffu, acc1[h], 2);
    }

    long R0 = (long)blockIdx.x * 128 + warp*16 + gid;
    int b = (int)(R0 >> 16);
    int i = (int)((R0 >> 8) & 255);
    int j0 = (int)(R0 & 255);
    int hA = tig*2, hB = hA + 1;

    float oA0 = gelu_exact(acc0[hA] + b3s[hA]);
    float oB0 = gelu_exact(acc0[hB] + b3s[hB]);
    float oA1 = gelu_exact(acc1[hA] + b3s[hA]);
    float oB1 = gelu_exact(acc1[hB] + b3s[hB]);

    long baseA = ((long)(b*8 + hA) << 16) + (i << 8);
    long baseB = ((long)(b*8 + hB) << 16) + (i << 8);
    biasOut[baseA + j0]     = oA0;
    biasOut[baseB + j0]     = oB0;
    biasOut[baseA + j0 + 8] = oA1;
    biasOut[baseB + j0 + 8] = oB1;
}

// ---------------- LayerNorm ----------------
__global__ __launch_bounds__(256) void ln_kernel(
    const float* __restrict__ x, const float* __restrict__ g,
    const float* __restrict__ bb, float* __restrict__ out)
{
    __shared__ float red[16];
    int r = blockIdx.x, t = threadIdx.x;
    float v = x[r*256 + t];

    float s = v;
#pragma unroll
    for (int o = 16; o > 0; o >>= 1) s += __shfl_xor_sync(0xffffffffu, s, o);
    if ((t & 31) == 0) red[t >> 5] = s;
    __syncthreads();
    float mu = 0.f;
#pragma unroll
    for (int w = 0; w < 8; w++) mu += red[w];
    mu *= (1.0f/256.0f);

    float d = v - mu;
    float q = d*d;
#pragma unroll
    for (int o = 16; o > 0; o >>= 1) q += __shfl_xor_sync(0xffffffffu, q, o);
    if ((t & 31) == 0) red[8 + (t >> 5)] = q;
    __syncthreads();
    float var = 0.f;
#pragma unroll
    for (int w = 0; w < 8; w++) var += red[8 + w];
    var *= (1.0f/256.0f);

    out[r*256 + t] = d * rsqrtf(var + 1e-5f) * g[t] + bb[t];
}

// ---------------- tf32 tensor-core GEMM v4: 128x128 tile, cp.async ----------
// C[M,N] = epi(A[M,K] @ B[K,N] + bias, res)
// Block 256 thr (8 warps = 4x2), tile 128x128, K-step 32, warp tile 32x64.
// EPI: 0 = +bias ; 1 = gelu(+bias) ; 2 = +bias +res ; 3 = gelu(+bias)+res
#define AS_STRIDE 36
#define BS_STRIDE 136
#define A_BUF (128*AS_STRIDE)
#define B_BUF (32*BS_STRIDE)
#define TG_SMEM ((2*A_BUF + 2*B_BUF)*4)
template<int EPI>
__global__ __launch_bounds__(256, 2) void tgemm_kernel(
    const float* __restrict__ A, const float* __restrict__ Bm,
    const float* __restrict__ bias, const float* __restrict__ res,
    float* __restrict__ C, int M, int Nn, int K)
{
    extern __shared__ float tsm[];
    float* As = tsm;                 // 2 bufs of 128*36
    float* Bs = tsm + 2*A_BUF;       // 2 bufs of 32*136

    int tid = threadIdx.x;
    int lane = tid & 31, warp = tid >> 5;
    int tig = lane & 3, gid = lane >> 2;
    int warp_m = warp & 3, warp_n = warp >> 2;

    int row0 = blockIdx.y * 128;
    int col0 = blockIdx.x * 128;

    // copy maps: A thread copies 16 floats of one row; B likewise.
    int ar = tid >> 1, ac = (tid & 1) * 16;
    int br = tid >> 3, bc = (tid & 7) * 16;

    const float* Ap = A + (long)(row0 + ar)*K + ac;
    const float* Bp = Bm + (long)br*Nn + col0 + bc;

    unsigned a_sb = sptr(&As[ar*AS_STRIDE + ac]);
    unsigned b_sb = sptr(&Bs[br*BS_STRIDE + bc]);

    float c[2][8][4];
#pragma unroll
    for (int mt = 0; mt < 2; mt++)
#pragma unroll
        for (int nt = 0; nt < 8; nt++)
#pragma unroll
            for (int q = 0; q < 4; q++) c[mt][nt][q] = 0.f;

    int iters = K >> 5;

    {
#pragma unroll
        for (int i = 0; i < 4; i++) cp16(a_sb + 16*i, Ap + 4*i);
#pragma unroll
        for (int i = 0; i < 4; i++) cp16(b_sb + 16*i, Bp + 4*i);
        asm volatile("cp.async.commit_group;");
    }

    for (int it = 0; it < iters; it++) {
        int buf = it & 1;
        if (it + 1 < iters) {
            int nbuf = buf ^ 1;
            const float* ag = Ap + (it + 1)*32;
#pragma unroll
            for (int i = 0; i < 4; i++) cp16(a_sb + nbuf*A_BUF*4 + 16*i, ag + 4*i);
            const float* bg = Bp + (long)(it + 1)*32*Nn;
#pragma unroll
            for (int i = 0; i < 4; i++) cp16(b_sb + nbuf*B_BUF*4 + 16*i, bg + 4*i);
            asm volatile("cp.async.commit_group;");
            asm volatile("cp.async.wait_group 1;");
        } else {
            asm volatile("cp.async.wait_group 0;");
        }
        __syncthreads();

        const float* aw0 = As + buf*A_BUF + (warp_m*32 + gid)*AS_STRIDE;
        const float* bw  = Bs + buf*B_BUF + warp_n*64 + gid;
#pragma unroll
        for (int kt = 0; kt < 4; kt++) {
            unsigned af[2][4];
#pragma unroll
            for (int mt = 0; mt < 2; mt++) {
                const float* aw = aw0 + mt*16*AS_STRIDE + kt*8;
                af[mt][0] = f2tf32(aw[tig]);
                af[mt][1] = f2tf32(aw[8*AS_STRIDE + tig]);
                af[mt][2] = f2tf32(aw[tig + 4]);
                af[mt][3] = f2tf32(aw[8*AS_STRIDE + tig + 4]);
            }
#pragma unroll
            for (int nt = 0; nt < 8; nt++) {
                const float* bww = bw + (kt*8 + tig)*BS_STRIDE + nt*8;
                unsigned b0 = f2tf32(bww[0]);
                unsigned b1 = f2tf32(bww[4*BS_STRIDE]);
#pragma unroll
                for (int mt = 0; mt < 2; mt++)
                    mma_tf32(c[mt][nt][0], c[mt][nt][1], c[mt][nt][2], c[mt][nt][3],
                             af[mt][0], af[mt][1], af[mt][2], af[mt][3], b0, b1);
            }
        }
        __syncthreads();
    }

    // epilogue
#pragma unroll
    for (int mt = 0; mt < 2; mt++) {
#pragma unroll
        for (int half = 0; half < 2; half++) {
            int r = row0 + warp_m*32 + mt*16 + gid + half*8;
#pragma unroll
            for (int nt = 0; nt < 8; nt++) {
                int cc = col0 + warp_n*64 + nt*8 + tig*2;
                float v0 = c[mt][nt][half*2 + 0] + bias[cc];
                float v1 = c[mt][nt][half*2 + 1] + bias[cc + 1];
                if (EPI == 1 || EPI == 3) { v0 = gelu_exact(v0); v1 = gelu_exact(v1); }
                if (EPI == 2 || EPI == 3) {
                    const float2 rr = *(const float2*)&res[(long)r*Nn + cc];
                    v0 += rr.x; v1 += rr.y;
                }
                *(float2*)&C[(long)r*Nn + cc] = make_float2(v0, v1);
            }
        }
    }
}

// ---------------- Fused attention v4 (reverted R11 best: 70.8us) ------------
// grid = 256 (2 blocks per (b,h)), block = 512 (16 warps), <=64 regs.
// q staged in per-warp smem (broadcast reads); scores accumulate d4-outer.
#define KVSTRIDE 36
#define ATTN_SMEM ((256*KVSTRIDE*2 + 16*512 + 16*64)*4)
__global__ __launch_bounds__(512, 2) void attn_kernel(
    const float* __restrict__ qkv, const float* __restrict__ biasT,
    const unsigned char* __restrict__ mask, float* __restrict__ xa)
{
    extern __shared__ float sm[];
    float* Ks = sm;                        // 256*36
    float* Vs = Ks + 256*KVSTRIDE;         // 256*36
    float* Ps = Vs + 256*KVSTRIDE;         // 16*512
    float* Qs = Ps + 16*512;               // 16*64

    int tid  = threadIdx.x;
    int warp = tid >> 5, lane = tid & 31;
    int blk = blockIdx.x;
    int bh = blk >> 1, itile = blk & 1;
    int b = bh >> 3, h = bh & 7;

    const float* base = qkv + (long)b*256*768 + h*32;

    for (int idx = tid; idx < 2048; idx += 512) {
        int row = idx >> 3, d4 = (idx & 7) << 2;
        const float* src = base + (long)row*768;
        *(float4*)&Ks[row*KVSTRIDE + d4] = *(const float4*)(src + 256 + d4);
        *(float4*)&Vs[row*KVSTRIDE + d4] = *(const float4*)(src + 512 + d4);
    }
    __syncthreads();

    unsigned mk = 0;
#pragma unroll
    for (int c = 0; c < 8; c++)
        if (mask[b*256 + c*32 + lane]) mk |= (1u << c);

    float* p0 = Ps + warp*512;
    float* p1 = p0 + 256;
    float4* qs4 = (float4*)(Qs + warp*64);
    const float scale = 0.17677669529663687f;   // 1/sqrt(32)

    for (int ii = 0; ii < 8; ii += 2) {
        int i0 = itile*128 + warp*8 + ii, i1 = i0 + 1;

        if (lane < 8)
            qs4[lane] = *((const float4*)(base + (long)i0*768) + lane);
        else if (lane < 16)
            qs4[lane] = *((const float4*)(base + (long)i1*768) + (lane - 8));
        __syncwarp();

        const float* br0 = biasT + ((long)(bh*256 + i0) << 8);
        const float* br1 = biasT + ((long)(bh*256 + i1) << 8);
        float bb0[8], bb1[8];
#pragma unroll
        for (int c = 0; c < 8; c++) {
            bb0[c] = br0[c*32 + lane];
            bb1[c] = br1[c*32 + lane];
        }

        float a0[8], a1[8];
#pragma unroll
        for (int c = 0; c < 8; c++) { a0[c] = 0.f; a1[c] = 0.f; }
#pragma unroll
        for (int d4 = 0; d4 < 8; d4++) {
            float4 qq0 = qs4[d4];
            float4 qq1 = qs4[8 + d4];
#pragma unroll
            for (int c = 0; c < 8; c++) {
                float4 k4 = *(const float4*)&Ks[(c*32 + lane)*KVSTRIDE + d4*4];
                a0[c] += qq0.x*k4.x + qq0.y*k4.y + qq0.z*k4.z + qq0.w*k4.w;
                a1[c] += qq1.x*k4.x + qq1.y*k4.y + qq1.z*k4.z + qq1.w*k4.w;
            }
        }
#pragma unroll
        for (int c = 0; c < 8; c++) {
            a0[c] = a0[c]*scale + bb0[c];
            a1[c] = a1[c]*scale + bb1[c];
            if ((mk >> c) & 1) { a0[c] = -1e30f; a1[c] = -1e30f; }
        }

        float m0 = a0[0], m1 = a1[0];
#pragma unroll
        for (int c = 1; c < 8; c++) { m0 = fmaxf(m0, a0[c]); m1 = fmaxf(m1, a1[c]); }
#pragma unroll
        for (int o = 16; o > 0; o >>= 1) {
            m0 = fmaxf(m0, __shfl_xor_sync(0xffffffffu, m0, o));
            m1 = fmaxf(m1, __shfl_xor_sync(0xffffffffu, m1, o));
        }
        float z0 = 0.f, z1 = 0.f;
#pragma unroll
        for (int c = 0; c < 8; c++) {
            a0[c] = __expf(a0[c] - m0);  z0 += a0[c];
            a1[c] = __expf(a1[c] - m1);  z1 += a1[c];
        }
#pragma unroll
        for (int o = 16; o > 0; o >>= 1) {
            z0 += __shfl_xor_sync(0xffffffffu, z0, o);
            z1 += __shfl_xor_sync(0xffffffffu, z1, o);
        }
        float rz0 = 1.0f / z0, rz1 = 1.0f / z1;

#pragma unroll
        for (int c = 0; c < 8; c++) { p0[c*32 + lane] = a0[c]; p1[c*32 + lane] = a1[c]; }
        __syncwarp();

        float acc0 = 0.f, acc1 = 0.f;
        const float4* p04 = (const float4*)p0;
        const float4* p14 = (const float4*)p1;
#pragma unroll
        for (int c = 0; c < 8; c++) {
#pragma unroll
            for (int j4 = 0; j4 < 8; j4++) {
                float4 P0 = p04[c*8 + j4];
                float4 P1 = p14[c*8 + j4];
                int j = c*32 + j4*4;
                float v0 = Vs[(j+0)*KVSTRIDE + lane];
                float v1 = Vs[(j+1)*KVSTRIDE + lane];
                float v2 = Vs[(j+2)*KVSTRIDE + lane];
                float v3 = Vs[(j+3)*KVSTRIDE + lane];
                acc0 += P0.x*v0 + P0.y*v1 + P0.z*v2 + P0.w*v3;
                acc1 += P1.x*v0 + P1.y*v1 + P1.z*v2 + P1.w*v3;
            }
        }
        __syncwarp();

        xa[(long)(b*256 + i0)*256 + h*32 + lane] = acc0 * rz0;
        xa[(long)(b*256 + i1)*256 + h*32 + lane] = acc1 * rz1;
    }
}

// ---------------- launch ----------------
extern "C" void kernel_launch(void* const* d_in, const int* in_sizes, int n_in,
                              void* d_out, int out_size)
{
    const float* x      = (const float*)d_in[0];
    const float* u      = (const float*)d_in[1];
    const unsigned char* mask = (const unsigned char*)d_in[2];
    const float* n1_g   = (const float*)d_in[3];
    const float* n1_b   = (const float*)d_in[4];
    const float* qkv_w  = (const float*)d_in[5];
    const float* qkv_b  = (const float*)d_in[6];
    const float* proj_w = (const float*)d_in[7];
    const float* proj_b = (const float*)d_in[8];
    const float* n2_g   = (const float*)d_in[9];
    const float* n2_b   = (const float*)d_in[10];
    const float* mlp_w1 = (const float*)d_in[11];
    const float* mlp_b1 = (const float*)d_in[12];
    const float* mlp_w2 = (const float*)d_in[13];
    const float* mlp_b2 = (const float*)d_in[14];
    const float* pw_w1  = (const float*)d_in[15];
    const float* pw_b1  = (const float*)d_in[16];
    const float* pw_w2  = (const float*)d_in[17];
    const float* pw_b2  = (const float*)d_in[18];
    const float* pw_w3  = (const float*)d_in[19];
    const float* pw_b3  = (const float*)d_in[20];
    float* out = (float*)d_out;

    float *xn, *qkvb, *biasT, *xa, *x1, *m1;
    cudaGetSymbolAddress((void**)&xn,    g_xn);
    cudaGetSymbolAddress((void**)&qkvb,  g_qkv);
    cudaGetSymbolAddress((void**)&biasT, g_biasT);
    cudaGetSymbolAddress((void**)&xa,    g_xa);
    cudaGetSymbolAddress((void**)&x1,    g_x1);
    cudaGetSymbolAddress((void**)&m1,    g_m1);

    // 1. pairwise MLP (tf32 mma) -> bias[B,H,N,N]
    int pw_smem = (128*H1S + 4096 + 512 + 64 + 8 + 256 + 64) * 4;
    cudaFuncSetAttribute(pairwise_kernel,
                         cudaFuncAttributeMaxDynamicSharedMemorySize, pw_smem);
    pairwise_kernel<<<PAIR_ROWS/128, 256, pw_smem>>>(u, pw_w1, pw_b1, pw_w2, pw_b2,
                                                     pw_w3, pw_b3, biasT);
    // 2. LN1
    ln_kernel<<<ROWS, 256>>>(x, n1_g, n1_b, xn);

    cudaFuncSetAttribute(tgemm_kernel<0>, cudaFuncAttributeMaxDynamicSharedMemorySize, TG_SMEM);
    cudaFuncSetAttribute(tgemm_kernel<1>, cudaFuncAttributeMaxDynamicSharedMemorySize, TG_SMEM);
    cudaFuncSetAttribute(tgemm_kernel<2>, cudaFuncAttributeMaxDynamicSharedMemorySize, TG_SMEM);
    cudaFuncSetAttribute(tgemm_kernel<3>, cudaFuncAttributeMaxDynamicSharedMemorySize, TG_SMEM);

    // 3. QKV GEMM (tf32)  [4096,256] x [256,768]
    tgemm_kernel<0><<<dim3(768/128, ROWS/128), 256, TG_SMEM>>>(xn, qkv_w, qkv_b, nullptr,
                                                               qkvb, ROWS, 768, 256);
    // 4. attention (reverted v4)
    cudaFuncSetAttribute(attn_kernel, cudaFuncAttributeMaxDynamicSharedMemorySize,
                         ATTN_SMEM);
    attn_kernel<<<BB*HH*2, 512, ATTN_SMEM>>>(qkvb, biasT, mask, xa);
    // 5. proj + residual -> x1  (tf32)
    tgemm_kernel<2><<<dim3(256/128, ROWS/128), 256, TG_SMEM>>>(xa, proj_w, proj_b, x,
                                                               x1, ROWS, 256, 256);
    // 6. LN2
    ln_kernel<<<ROWS, 256>>>(x1, n2_g, n2_b, xn);
    // 7. MLP1 + gelu (tf32)
    tgemm_kernel<1><<<dim3(1024/128, ROWS/128), 256, TG_SMEM>>>(xn, mlp_w1, mlp_b1, nullptr,
                                                                m1, ROWS, 1024, 256);
    // 8. MLP2 + gelu + residual -> out (tf32)
    tgemm_kernel<3><<<dim3(256/128, ROWS/128), 256, TG_SMEM>>>(m1, mlp_w2, mlp_b2, x1,
                                                               out, ROWS, 256, 1024);
}

// round 15
// speedup vs baseline: 1.0735x; 1.0735x over previous
#include <cuda_runtime.h>
#include <cuda_bf16.h>
#include <math.h>

// Shapes
#define BB 16
#define NN 256
#define DD 256
#define HH 8
#define HD 32
#define PD 4
#define RATIO 4
#define ROWS (BB*NN)            // 4096
#define PAIR_ROWS (BB*NN*NN)    // 1048576

// ---------------- scratch (device globals, no allocation) ----------------
__device__ float g_xn [ROWS*DD];        // 4 MB
__device__ float g_qkv[ROWS*3*DD];      // 12 MB
__device__ float g_biasT[BB*HH*NN*NN];  // 33.5 MB  [B,H,N,N]
__device__ float g_xa [ROWS*DD];        // 4 MB  [B,N,H*HD]
__device__ float g_x1 [ROWS*DD];        // 4 MB
__device__ float g_m1 [ROWS*RATIO*DD];  // 16 MB

// Branchless gelu via Abramowitz-Stegun 7.1.26 erf (|eps| <= 1.5e-7).
__device__ __forceinline__ float gelu_exact(float x) {
    float z  = x * 0.70710678118654752f;
    float az = fabsf(z);
    float t  = __fdividef(1.0f, fmaf(0.3275911f, az, 1.0f));
    float p  = t*(0.254829592f + t*(-0.284496736f + t*(1.421413741f
                  + t*(-1.453152027f + t*1.061405429f))));
    float e  = __expf(-az*az);
    float erfv = copysignf(fmaf(-p, e, 1.0f), z);
    return 0.5f*x*(1.0f + erfv);
}

__device__ __forceinline__ unsigned f2tf32(float x) {
    unsigned r;
    asm("cvt.rna.tf32.f32 %0, %1;" : "=r"(r) : "f"(x));
    return r;
}

__device__ __forceinline__ void mma_tf32(
    float& c0, float& c1, float& c2, float& c3,
    unsigned a0, unsigned a1, unsigned a2, unsigned a3,
    unsigned b0, unsigned b1)
{
    asm volatile(
        "mma.sync.aligned.m16n8k8.row.col.f32.tf32.tf32.f32 "
        "{%0,%1,%2,%3}, {%4,%5,%6,%7}, {%8,%9}, {%0,%1,%2,%3};"
        : "+f"(c0), "+f"(c1), "+f"(c2), "+f"(c3)
        : "r"(a0), "r"(a1), "r"(a2), "r"(a3), "r"(b0), "r"(b1));
}

__device__ __forceinline__ unsigned sptr(const void* p) {
    return (unsigned)__cvta_generic_to_shared(p);
}
__device__ __forceinline__ void cp16(unsigned s, const float* g) {
    asm volatile("cp.async.cg.shared.global [%0], [%1], 16;" :: "r"(s), "l"(g));
}

// ---------------- pairwise MLP (tf32 tensor cores) ----------------
#define H1S 68   // smem row stride for h1 (conflict-free fragment loads)
__global__ __launch_bounds__(256) void pairwise_kernel(
    const float* __restrict__ u,
    const float* __restrict__ w1, const float* __restrict__ b1,
    const float* __restrict__ w2, const float* __restrict__ b2,
    const float* __restrict__ w3, const float* __restrict__ b3,
    float* __restrict__ biasOut)
{
    extern __shared__ float dsm[];
    unsigned* h1s = (unsigned*)dsm;                 // 128*68
    unsigned* w2f = h1s + 128*H1S;                  // 4096 (fragment layout)
    float*    w3s = (float*)(w2f + 4096);           // 512
    float*    b2s = w3s + 512;                      // 64
    float*    b3s = b2s + 64;                       // 8
    float*    w1s = b3s + 8;                        // 256
    float*    b1s = w1s + 256;                      // 64

    int tid = threadIdx.x;
    int lane = tid & 31, warp = tid >> 5;
    int tig = lane & 3, gid = lane >> 2;

    if (tid < 64)  b1s[tid] = b1[tid];
    if (tid < 64)  b2s[tid] = b2[tid];
    if (tid < 8)   b3s[tid] = b3[tid];
    w1s[tid] = w1[tid];
    for (int i = tid; i < 512; i += 256) w3s[i] = w3[i];
    for (int idx = tid; idx < 4096; idx += 256) {
        int tile = idx >> 6;          // kt*8 + nt
        int pos  = idx & 63;
        int l    = pos >> 1, which = pos & 1;
        int kt = tile >> 3, nt = tile & 7;
        int ltig = l & 3, lgid = l >> 2;
        int k = kt*8 + ltig + which*4;
        int n = nt*8 + lgid;
        w2f[tile*64 + l*2 + which] = f2tf32(w2[k*64 + n]);
    }

    {
        int row = tid >> 1;                 // 0..127
        int c0  = (tid & 1) * 32;
        long gr = (long)blockIdx.x * 128 + row;
        float4 uv = ((const float4*)u)[gr];
        unsigned* dst = h1s + row*H1S + c0;
#pragma unroll
        for (int cc = 0; cc < 32; cc += 4) {
            unsigned pk[4];
#pragma unroll
            for (int q = 0; q < 4; q++) {
                int c = c0 + cc + q;
                float t = b1s[c] + uv.x*w1s[c] + uv.y*w1s[64+c]
                                 + uv.z*w1s[128+c] + uv.w*w1s[192+c];
                pk[q] = f2tf32(gelu_exact(t));
            }
            *(uint4*)&dst[cc] = make_uint4(pk[0], pk[1], pk[2], pk[3]);
        }
    }
    __syncthreads();

    float c[8][4];
#pragma unroll
    for (int nt = 0; nt < 8; nt++)
#pragma unroll
        for (int q = 0; q < 4; q++) c[nt][q] = 0.f;

    const unsigned* h1w = h1s + (warp*16 + gid)*H1S;
#pragma unroll
    for (int kt = 0; kt < 8; kt++) {
        unsigned a0 = h1w[kt*8 + tig];
        unsigned a1 = h1w[8*H1S + kt*8 + tig];
        unsigned a2 = h1w[kt*8 + tig + 4];
        unsigned a3 = h1w[8*H1S + kt*8 + tig + 4];
        const uint2* bf = (const uint2*)(w2f + kt*8*64);
#pragma unroll
        for (int nt = 0; nt < 8; nt++) {
            uint2 b = bf[nt*32 + lane];
            mma_tf32(c[nt][0], c[nt][1], c[nt][2], c[nt][3],
                     a0, a1, a2, a3, b.x, b.y);
        }
    }

    float acc0[8], acc1[8];
#pragma unroll
    for (int h = 0; h < 8; h++) { acc0[h] = 0.f; acc1[h] = 0.f; }

#pragma unroll
    for (int nt = 0; nt < 8; nt++) {
        int col0 = nt*8 + tig*2;
        float g00 = gelu_exact(c[nt][0] + b2s[col0]);
        float g01 = gelu_exact(c[nt][1] + b2s[col0+1]);
        float g10 = gelu_exact(c[nt][2] + b2s[col0]);
        float g11 = gelu_exact(c[nt][3] + b2s[col0+1]);
        const float4* w3r = (const float4*)&w3s[col0*8];
        float4 wa0 = w3r[0], wa1 = w3r[1];
        float4 wb0 = w3r[2], wb1 = w3r[3];
        acc0[0] += g00*wa0.x + g01*wb0.x;  acc1[0] += g10*wa0.x + g11*wb0.x;
        acc0[1] += g00*wa0.y + g01*wb0.y;  acc1[1] += g10*wa0.y + g11*wb0.y;
        acc0[2] += g00*wa0.z + g01*wb0.z;  acc1[2] += g10*wa0.z + g11*wb0.z;
        acc0[3] += g00*wa0.w + g01*wb0.w;  acc1[3] += g10*wa0.w + g11*wb0.w;
        acc0[4] += g00*wa1.x + g01*wb1.x;  acc1[4] += g10*wa1.x + g11*wb1.x;
        acc0[5] += g00*wa1.y + g01*wb1.y;  acc1[5] += g10*wa1.y + g11*wb1.y;
        acc0[6] += g00*wa1.z + g01*wb1.z;  acc1[6] += g10*wa1.z + g11*wb1.z;
        acc0[7] += g00*wa1.w + g01*wb1.w;  acc1[7] += g10*wa1.w + g11*wb1.w;
    }

#pragma unroll
    for (int h = 0; h < 8; h++) {
        acc0[h] += __shfl_xor_sync(0xffffffffu, acc0[h], 1);
        acc1[h] += __shfl_xor_sync(0xffffffffu, acc1[h], 1);
    }
#pragma unroll
    for (int h = 0; h < 8; h++) {
        acc0[h] += __shfl_xor_sync(0xffffffffu, acc0[h], 2);
        acc1[h] += __shfl_xor_sync(0xffffffffu, acc1[h], 2);
    }

    long R0 = (long)blockIdx.x * 128 + warp*16 + gid;
    int b = (int)(R0 >> 16);
    int i = (int)((R0 >> 8) & 255);
    int j0 = (int)(R0 & 255);
    int hA = tig*2, hB = hA + 1;

    float oA0 = gelu_exact(acc0[hA] + b3s[hA]);
    float oB0 = gelu_exact(acc0[hB] + b3s[hB]);
    float oA1 = gelu_exact(acc1[hA] + b3s[hA]);
    float oB1 = gelu_exact(acc1[hB] + b3s[hB]);

    long baseA = ((long)(b*8 + hA) << 16) + (i << 8);
    long baseB = ((long)(b*8 + hB) << 16) + (i << 8);
    biasOut[baseA + j0]     = oA0;
    biasOut[baseB + j0]     = oB0;
    biasOut[baseA + j0 + 8] = oA1;
    biasOut[baseB + j0 + 8] = oB1;
}

// ---------------- LayerNorm ----------------
__global__ __launch_bounds__(256) void ln_kernel(
    const float* __restrict__ x, const float* __restrict__ g,
    const float* __restrict__ bb, float* __restrict__ out)
{
    __shared__ float red[16];
    int r = blockIdx.x, t = threadIdx.x;
    float v = x[r*256 + t];

    float s = v;
#pragma unroll
    for (int o = 16; o > 0; o >>= 1) s += __shfl_xor_sync(0xffffffffu, s, o);
    if ((t & 31) == 0) red[t >> 5] = s;
    __syncthreads();
    float mu = 0.f;
#pragma unroll
    for (int w = 0; w < 8; w++) mu += red[w];
    mu *= (1.0f/256.0f);

    float d = v - mu;
    float q = d*d;
#pragma unroll
    for (int o = 16; o > 0; o >>= 1) q += __shfl_xor_sync(0xffffffffu, q, o);
    if ((t & 31) == 0) red[8 + (t >> 5)] = q;
    __syncthreads();
    float var = 0.f;
#pragma unroll
    for (int w = 0; w < 8; w++) var += red[8 + w];
    var *= (1.0f/256.0f);

    out[r*256 + t] = d * rsqrtf(var + 1e-5f) * g[t] + bb[t];
}

// ---------------- tf32 tensor-core GEMM (R11 proven: 128x64, cp.async) ------
#define AS_STRIDE 36
#define BS_STRIDE 72
#define A_BUF (128*AS_STRIDE)
#define B_BUF (32*BS_STRIDE)
#define TG_SMEM ((2*A_BUF + 2*B_BUF)*4)
template<int EPI>
__global__ __launch_bounds__(256, 2) void tgemm_kernel(
    const float* __restrict__ A, const float* __restrict__ Bm,
    const float* __restrict__ bias, const float* __restrict__ res,
    float* __restrict__ C, int M, int Nn, int K)
{
    extern __shared__ float tsm[];
    float* As = tsm;                 // 2 bufs of 128*36
    float* Bs = tsm + 2*A_BUF;       // 2 bufs of 32*72

    int tid = threadIdx.x;
    int lane = tid & 31, warp = tid >> 5;
    int tig = lane & 3, gid = lane >> 2;
    int warp_m = warp & 3, warp_n = warp >> 2;

    int row0 = blockIdx.y * 128;
    int col0 = blockIdx.x * 64;

    int ar = tid >> 1, ac = (tid & 1) * 16;
    int br = tid >> 3, bc = (tid & 7) * 8;

    const float* Ap = A + (long)(row0 + ar)*K + ac;
    const float* Bp = Bm + (long)br*Nn + col0 + bc;

    unsigned a_sb = sptr(&As[ar*AS_STRIDE + ac]);
    unsigned b_sb = sptr(&Bs[br*BS_STRIDE + bc]);

    float c[2][4][4];
#pragma unroll
    for (int mt = 0; mt < 2; mt++)
#pragma unroll
        for (int nt = 0; nt < 4; nt++)
#pragma unroll
            for (int q = 0; q < 4; q++) c[mt][nt][q] = 0.f;

    int iters = K >> 5;

    {
#pragma unroll
        for (int i = 0; i < 4; i++) cp16(a_sb + 16*i, Ap + 4*i);
#pragma unroll
        for (int i = 0; i < 2; i++) cp16(b_sb + 16*i, Bp + 4*i);
        asm volatile("cp.async.commit_group;");
    }

    for (int it = 0; it < iters; it++) {
        int buf = it & 1;
        if (it + 1 < iters) {
            int nbuf = buf ^ 1;
            const float* ag = Ap + (it + 1)*32;
#pragma unroll
            for (int i = 0; i < 4; i++) cp16(a_sb + nbuf*A_BUF*4 + 16*i, ag + 4*i);
            const float* bg = Bp + (long)(it + 1)*32*Nn;
#pragma unroll
            for (int i = 0; i < 2; i++) cp16(b_sb + nbuf*B_BUF*4 + 16*i, bg + 4*i);
            asm volatile("cp.async.commit_group;");
            asm volatile("cp.async.wait_group 1;");
        } else {
            asm volatile("cp.async.wait_group 0;");
        }
        __syncthreads();

        const float* aw0 = As + buf*A_BUF + (warp_m*32 + gid)*AS_STRIDE;
        const float* bw  = Bs + buf*B_BUF + warp_n*32 + gid;
#pragma unroll
        for (int kt = 0; kt < 4; kt++) {
            unsigned af[2][4];
#pragma unroll
            for (int mt = 0; mt < 2; mt++) {
                const float* aw = aw0 + mt*16*AS_STRIDE + kt*8;
                af[mt][0] = f2tf32(aw[tig]);
                af[mt][1] = f2tf32(aw[8*AS_STRIDE + tig]);
                af[mt][2] = f2tf32(aw[tig + 4]);
                af[mt][3] = f2tf32(aw[8*AS_STRIDE + tig + 4]);
            }
#pragma unroll
            for (int nt = 0; nt < 4; nt++) {
                const float* bww = bw + (kt*8 + tig)*BS_STRIDE + nt*8;
                unsigned b0 = f2tf32(bww[0]);
                unsigned b1 = f2tf32(bww[4*BS_STRIDE]);
#pragma unroll
                for (int mt = 0; mt < 2; mt++)
                    mma_tf32(c[mt][nt][0], c[mt][nt][1], c[mt][nt][2], c[mt][nt][3],
                             af[mt][0], af[mt][1], af[mt][2], af[mt][3], b0, b1);
            }
        }
        __syncthreads();
    }

#pragma unroll
    for (int mt = 0; mt < 2; mt++) {
#pragma unroll
        for (int half = 0; half < 2; half++) {
            int r = row0 + warp_m*32 + mt*16 + gid + half*8;
#pragma unroll
            for (int nt = 0; nt < 4; nt++) {
                int cc = col0 + warp_n*32 + nt*8 + tig*2;
                float v0 = c[mt][nt][half*2 + 0] + bias[cc];
                float v1 = c[mt][nt][half*2 + 1] + bias[cc + 1];
                if (EPI == 1 || EPI == 3) { v0 = gelu_exact(v0); v1 = gelu_exact(v1); }
                if (EPI == 2 || EPI == 3) {
                    const float2 rr = *(const float2*)&res[(long)r*Nn + cc];
                    v0 += rr.x; v1 += rr.y;
                }
                *(float2*)&C[(long)r*Nn + cc] = make_float2(v0, v1);
            }
        }
    }
}

// ---------------- Fused attention v4 (proven 70.8us) -------------------------
#define KVSTRIDE 36
#define ATTN_SMEM ((256*KVSTRIDE*2 + 16*512 + 16*64)*4)
__global__ __launch_bounds__(512, 2) void attn_kernel(
    const float* __restrict__ qkv, const float* __restrict__ biasT,
    const unsigned char* __restrict__ mask, float* __restrict__ xa)
{
    extern __shared__ float sm[];
    float* Ks = sm;                        // 256*36
    float* Vs = Ks + 256*KVSTRIDE;         // 256*36
    float* Ps = Vs + 256*KVSTRIDE;         // 16*512
    float* Qs = Ps + 16*512;               // 16*64

    int tid  = threadIdx.x;
    int warp = tid >> 5, lane = tid & 31;
    int blk = blockIdx.x;
    int bh = blk >> 1, itile = blk & 1;
    int b = bh >> 3, h = bh & 7;

    const float* base = qkv + (long)b*256*768 + h*32;

    for (int idx = tid; idx < 2048; idx += 512) {
        int row = idx >> 3, d4 = (idx & 7) << 2;
        const float* src = base + (long)row*768;
        *(float4*)&Ks[row*KVSTRIDE + d4] = *(const float4*)(src + 256 + d4);
        *(float4*)&Vs[row*KVSTRIDE + d4] = *(const float4*)(src + 512 + d4);
    }
    __syncthreads();

    unsigned mk = 0;
#pragma unroll
    for (int c = 0; c < 8; c++)
        if (mask[b*256 + c*32 + lane]) mk |= (1u << c);

    float* p0 = Ps + warp*512;
    float* p1 = p0 + 256;
    float4* qs4 = (float4*)(Qs + warp*64);
    const float scale = 0.17677669529663687f;   // 1/sqrt(32)

    for (int ii = 0; ii < 8; ii += 2) {
        int i0 = itile*128 + warp*8 + ii, i1 = i0 + 1;

        if (lane < 8)
            qs4[lane] = *((const float4*)(base + (long)i0*768) + lane);
        else if (lane < 16)
            qs4[lane] = *((const float4*)(base + (long)i1*768) + (lane - 8));
        __syncwarp();

        const float* br0 = biasT + ((long)(bh*256 + i0) << 8);
        const float* br1 = biasT + ((long)(bh*256 + i1) << 8);
        float bb0[8], bb1[8];
#pragma unroll
        for (int c = 0; c < 8; c++) {
            bb0[c] = br0[c*32 + lane];
            bb1[c] = br1[c*32 + lane];
        }

        float a0[8], a1[8];
#pragma unroll
        for (int c = 0; c < 8; c++) { a0[c] = 0.f; a1[c] = 0.f; }
#pragma unroll
        for (int d4 = 0; d4 < 8; d4++) {
            float4 qq0 = qs4[d4];
            float4 qq1 = qs4[8 + d4];
#pragma unroll
            for (int c = 0; c < 8; c++) {
                float4 k4 = *(const float4*)&Ks[(c*32 + lane)*KVSTRIDE + d4*4];
                a0[c] += qq0.x*k4.x + qq0.y*k4.y + qq0.z*k4.z + qq0.w*k4.w;
                a1[c] += qq1.x*k4.x + qq1.y*k4.y + qq1.z*k4.z + qq1.w*k4.w;
            }
        }
#pragma unroll
        for (int c = 0; c < 8; c++) {
            a0[c] = a0[c]*scale + bb0[c];
            a1[c] = a1[c]*scale + bb1[c];
            if ((mk >> c) & 1) { a0[c] = -1e30f; a1[c] = -1e30f; }
        }

        float m0 = a0[0], m1 = a1[0];
#pragma unroll
        for (int c = 1; c < 8; c++) { m0 = fmaxf(m0, a0[c]); m1 = fmaxf(m1, a1[c]); }
#pragma unroll
        for (int o = 16; o > 0; o >>= 1) {
            m0 = fmaxf(m0, __shfl_xor_sync(0xffffffffu, m0, o));
            m1 = fmaxf(m1, __shfl_xor_sync(0xffffffffu, m1, o));
        }
        float z0 = 0.f, z1 = 0.f;
#pragma unroll
        for (int c = 0; c < 8; c++) {
            a0[c] = __expf(a0[c] - m0);  z0 += a0[c];
            a1[c] = __expf(a1[c] - m1);  z1 += a1[c];
        }
#pragma unroll
        for (int o = 16; o > 0; o >>= 1) {
            z0 += __shfl_xor_sync(0xffffffffu, z0, o);
            z1 += __shfl_xor_sync(0xffffffffu, z1, o);
        }
        float rz0 = 1.0f / z0, rz1 = 1.0f / z1;

#pragma unroll
        for (int c = 0; c < 8; c++) { p0[c*32 + lane] = a0[c]; p1[c*32 + lane] = a1[c]; }
        __syncwarp();

        float acc0 = 0.f, acc1 = 0.f;
        const float4* p04 = (const float4*)p0;
        const float4* p14 = (const float4*)p1;
#pragma unroll
        for (int c = 0; c < 8; c++) {
#pragma unroll
            for (int j4 = 0; j4 < 8; j4++) {
                float4 P0 = p04[c*8 + j4];
                float4 P1 = p14[c*8 + j4];
                int j = c*32 + j4*4;
                float v0 = Vs[(j+0)*KVSTRIDE + lane];
                float v1 = Vs[(j+1)*KVSTRIDE + lane];
                float v2 = Vs[(j+2)*KVSTRIDE + lane];
                float v3 = Vs[(j+3)*KVSTRIDE + lane];
                acc0 += P0.x*v0 + P0.y*v1 + P0.z*v2 + P0.w*v3;
                acc1 += P1.x*v0 + P1.y*v1 + P1.z*v2 + P1.w*v3;
            }
        }
        __syncwarp();

        xa[(long)(b*256 + i0)*256 + h*32 + lane] = acc0 * rz0;
        xa[(long)(b*256 + i1)*256 + h*32 + lane] = acc1 * rz1;
    }
}

// ---------------- launch (2-branch graph: pairwise || LN1+QKV) ---------------
extern "C" void kernel_launch(void* const* d_in, const int* in_sizes, int n_in,
                              void* d_out, int out_size)
{
    const float* x      = (const float*)d_in[0];
    const float* u      = (const float*)d_in[1];
    const unsigned char* mask = (const unsigned char*)d_in[2];
    const float* n1_g   = (const float*)d_in[3];
    const float* n1_b   = (const float*)d_in[4];
    const float* qkv_w  = (const float*)d_in[5];
    const float* qkv_b  = (const float*)d_in[6];
    const float* proj_w = (const float*)d_in[7];
    const float* proj_b = (const float*)d_in[8];
    const float* n2_g   = (const float*)d_in[9];
    const float* n2_b   = (const float*)d_in[10];
    const float* mlp_w1 = (const float*)d_in[11];
    const float* mlp_b1 = (const float*)d_in[12];
    const float* mlp_w2 = (const float*)d_in[13];
    const float* mlp_b2 = (const float*)d_in[14];
    const float* pw_w1  = (const float*)d_in[15];
    const float* pw_b1  = (const float*)d_in[16];
    const float* pw_w2  = (const float*)d_in[17];
    const float* pw_b2  = (const float*)d_in[18];
    const float* pw_w3  = (const float*)d_in[19];
    const float* pw_b3  = (const float*)d_in[20];
    float* out = (float*)d_out;

    float *xn, *qkvb, *biasT, *xa, *x1, *m1;
    cudaGetSymbolAddress((void**)&xn,    g_xn);
    cudaGetSymbolAddress((void**)&qkvb,  g_qkv);
    cudaGetSymbolAddress((void**)&biasT, g_biasT);
    cudaGetSymbolAddress((void**)&xa,    g_xa);
    cudaGetSymbolAddress((void**)&x1,    g_x1);
    cudaGetSymbolAddress((void**)&m1,    g_m1);

    // one-time handle creation (host-side infra; no device memory, created on
    // the uncaptured correctness call, reused identically every call after)
    static cudaStream_t s1 = nullptr;
    static cudaEvent_t ev_fork = nullptr, ev_join = nullptr;
    if (s1 == nullptr) {
        cudaStreamCreateWithFlags(&s1, cudaStreamNonBlocking);
        cudaEventCreateWithFlags(&ev_fork, cudaEventDisableTiming);
        cudaEventCreateWithFlags(&ev_join, cudaEventDisableTiming);
    }

    int pw_smem = (128*H1S + 4096 + 512 + 64 + 8 + 256 + 64) * 4;
    cudaFuncSetAttribute(pairwise_kernel,
                         cudaFuncAttributeMaxDynamicSharedMemorySize, pw_smem);
    cudaFuncSetAttribute(tgemm_kernel<0>, cudaFuncAttributeMaxDynamicSharedMemorySize, TG_SMEM);
    cudaFuncSetAttribute(tgemm_kernel<1>, cudaFuncAttributeMaxDynamicSharedMemorySize, TG_SMEM);
    cudaFuncSetAttribute(tgemm_kernel<2>, cudaFuncAttributeMaxDynamicSharedMemorySize, TG_SMEM);
    cudaFuncSetAttribute(tgemm_kernel<3>, cudaFuncAttributeMaxDynamicSharedMemorySize, TG_SMEM);
    cudaFuncSetAttribute(attn_kernel, cudaFuncAttributeMaxDynamicSharedMemorySize, ATTN_SMEM);

    // fork: pairwise on s1, LN1+QKV on main stream
    cudaEventRecord(ev_fork, 0);
    cudaStreamWaitEvent(s1, ev_fork, 0);

    pairwise_kernel<<<PAIR_ROWS/128, 256, pw_smem, s1>>>(
        u, pw_w1, pw_b1, pw_w2, pw_b2, pw_w3, pw_b3, biasT);
    cudaEventRecord(ev_join, s1);

    ln_kernel<<<ROWS, 256>>>(x, n1_g, n1_b, xn);
    tgemm_kernel<0><<<dim3(768/64, ROWS/128), 256, TG_SMEM>>>(xn, qkv_w, qkv_b, nullptr,
                                                              qkvb, ROWS, 768, 256);

    // join: attention needs both qkv and biasT
    cudaStreamWaitEvent(0, ev_join, 0);

    attn_kernel<<<BB*HH*2, 512, ATTN_SMEM>>>(qkvb, biasT, mask, xa);
    tgemm_kernel<2><<<dim3(256/64, ROWS/128), 256, TG_SMEM>>>(xa, proj_w, proj_b, x,
                                                              x1, ROWS, 256, 256);
    ln_kernel<<<ROWS, 256>>>(x1, n2_g, n2_b, xn);
    tgemm_kernel<1><<<dim3(1024/64, ROWS/128), 256, TG_SMEM>>>(xn, mlp_w1, mlp_b1, nullptr,
                                                               m1, ROWS, 1024, 256);
    tgemm_kernel<3><<<dim3(256/64, ROWS/128), 256, TG_SMEM>>>(m1, mlp_w2, mlp_b2, x1,
                                                              out, ROWS, 256, 1024);
}